// round 1
// baseline (speedup 1.0000x reference)
#include <cuda_runtime.h>
#include <math.h>

#define D   128
#define CH  7
#define NC  8
#define NS  4
#define MAXM  40000
#define MAXET 680000

// ---------------- scratch (static device globals; no allocation) -------------
__device__ int   g_count[MAXM + 1];
__device__ int   g_off[MAXM + 1];
__device__ int   g_cursor[MAXM];
__device__ int   g_csr[MAXET];
__device__ float g_xl[(size_t)MAXM * D];
__device__ float g_xr[(size_t)MAXM * D];
__device__ float g_h [(size_t)MAXM * D];
__device__ float g_h2[(size_t)MAXM * D];
__device__ float g_s1[MAXM * CH];
__device__ float g_s2[MAXM * CH];
__device__ float g_lg[MAXM * CH];

// ---------------- CSR build --------------------------------------------------
__global__ void k_hist(const int* __restrict__ tgt, int E, int M) {
    int stride = gridDim.x * blockDim.x;
    int ET = E + M;
    for (int i = blockIdx.x * blockDim.x + threadIdx.x; i < ET; i += stride) {
        int t = (i < E) ? tgt[i] : (i - E);
        atomicAdd(&g_count[t], 1);
    }
}

__global__ void k_scan(int M) {  // single block, 1024 threads
    __shared__ int sh[1024];
    int tid = threadIdx.x;
    int chunk = (M + 1023) >> 10;
    int beg = tid * chunk;
    int end = min(beg + chunk, M);
    int s = 0;
    for (int i = beg; i < end; i++) s += g_count[i];
    sh[tid] = s;
    __syncthreads();
    // Hillis-Steele inclusive scan
    for (int o = 1; o < 1024; o <<= 1) {
        int v = (tid >= o) ? sh[tid - o] : 0;
        __syncthreads();
        sh[tid] += v;
        __syncthreads();
    }
    int run = sh[tid] - s;  // exclusive prefix for this chunk
    for (int i = beg; i < end; i++) {
        g_off[i] = run;
        g_cursor[i] = run;
        run += g_count[i];
    }
    if (tid == 1023) g_off[M] = sh[1023];
}

__global__ void k_scatter(const int* __restrict__ src, const int* __restrict__ tgt,
                          int E, int M) {
    int stride = gridDim.x * blockDim.x;
    int ET = E + M;
    for (int i = blockIdx.x * blockDim.x + threadIdx.x; i < ET; i += stride) {
        int t, s;
        if (i < E) { t = tgt[i]; s = src[i]; }
        else       { t = i - E;  s = i - E; }
        int pos = atomicAdd(&g_cursor[t], 1);
        g_csr[pos] = s;
    }
}

// sort each segment ascending by src -> CSR is deterministic regardless of
// atomic arrival order (duplicates are adjacent, so fp sums are bitwise stable)
__global__ void k_sortseg(int M) {
    int t = blockIdx.x * blockDim.x + threadIdx.x;
    if (t >= M) return;
    int beg = g_off[t], end = g_off[t + 1];
    for (int i = beg + 1; i < end; i++) {
        int v = g_csr[i];
        int j = i - 1;
        while (j >= beg && g_csr[j] > v) { g_csr[j + 1] = g_csr[j]; j--; }
        g_csr[j + 1] = v;
    }
}

// ---------------- SGEMM: C[M,128] = A[M,128] @ W[128,128] + bias -------------
// 128x128 tile, whole K in smem, 256 threads, 8x8 register tiles.
__global__ void k_sgemm(const float* __restrict__ A, const float* __restrict__ W,
                        const float* __restrict__ bias, float* __restrict__ C, int M) {
    extern __shared__ float sm[];
    float* XsT = sm;             // [128][128]  XsT[k][r]
    float* Ws  = sm + D * D;     // [128][128]  Ws[k][n]
    int tid  = threadIdx.x;
    int row0 = blockIdx.x * 128;

    // load W (row-major k,n) straight in
    for (int i = tid * 4; i < D * D; i += 256 * 4)
        *(float4*)&Ws[i] = *(const float4*)&W[i];

    // load X transposed: 2 threads per row
    {
        int r = tid >> 1, half = tid & 1;
        int row = row0 + r;
        bool valid = row < M;
        const float* arow = A + (size_t)row * D + half * 64;
        #pragma unroll
        for (int q = 0; q < 16; q++) {
            float4 v = valid ? *(const float4*)(arow + q * 4)
                             : make_float4(0.f, 0.f, 0.f, 0.f);
            int k = half * 64 + q * 4;
            XsT[(k + 0) * D + r] = v.x;
            XsT[(k + 1) * D + r] = v.y;
            XsT[(k + 2) * D + r] = v.z;
            XsT[(k + 3) * D + r] = v.w;
        }
    }
    __syncthreads();

    int tx = tid & 15, ty = tid >> 4;
    float acc[8][8];
    #pragma unroll
    for (int i = 0; i < 8; i++)
        #pragma unroll
        for (int j = 0; j < 8; j++) acc[i][j] = 0.f;

    #pragma unroll 8
    for (int k = 0; k < D; k++) {
        float a[8], b[8];
        *(float4*)(a)     = *(float4*)&XsT[k * D + ty * 8];
        *(float4*)(a + 4) = *(float4*)&XsT[k * D + ty * 8 + 4];
        *(float4*)(b)     = *(float4*)&Ws [k * D + tx * 8];
        *(float4*)(b + 4) = *(float4*)&Ws [k * D + tx * 8 + 4];
        #pragma unroll
        for (int i = 0; i < 8; i++)
            #pragma unroll
            for (int j = 0; j < 8; j++) acc[i][j] += a[i] * b[j];
    }

    float bv[8];
    *(float4*)(bv)     = *(const float4*)&bias[tx * 8];
    *(float4*)(bv + 4) = *(const float4*)&bias[tx * 8 + 4];
    #pragma unroll
    for (int i = 0; i < 8; i++) {
        int row = row0 + ty * 8 + i;
        if (row >= M) break;
        float o[8];
        #pragma unroll
        for (int j = 0; j < 8; j++) o[j] = acc[i][j] + bv[j];
        *(float4*)&C[(size_t)row * D + tx * 8]     = *(float4*)(o);
        *(float4*)&C[(size_t)row * D + tx * 8 + 4] = *(float4*)(o + 4);
    }
}

// ---------------- GATv2 aggregate, Dout=128: one warp per target node --------
__global__ void k_gat128(const float* __restrict__ xl, const float* __restrict__ xr,
                         const float* __restrict__ att, const float* __restrict__ bias,
                         float* __restrict__ out, int M, float slope) {
    int w = (blockIdx.x * blockDim.x + threadIdx.x) >> 5;
    int lane = threadIdx.x & 31;
    if (w >= M) return;

    float4 xr4 = *(const float4*)(xr + (size_t)w * D + lane * 4);
    float4 at4 = *(const float4*)(att + lane * 4);
    int beg = g_off[w], end = g_off[w + 1];

    float m = -INFINITY, d = 0.f;
    float4 acc = make_float4(0.f, 0.f, 0.f, 0.f);

    for (int e = beg; e < end; e++) {
        int s = g_csr[e];
        float4 a = *(const float4*)(xl + (size_t)s * D + lane * 4);
        float t0 = a.x + xr4.x; t0 = (t0 > 0.f) ? t0 : 0.2f * t0;
        float t1 = a.y + xr4.y; t1 = (t1 > 0.f) ? t1 : 0.2f * t1;
        float t2 = a.z + xr4.z; t2 = (t2 > 0.f) ? t2 : 0.2f * t2;
        float t3 = a.w + xr4.w; t3 = (t3 > 0.f) ? t3 : 0.2f * t3;
        float p = t0 * at4.x + t1 * at4.y + t2 * at4.z + t3 * at4.w;
        #pragma unroll
        for (int o = 16; o; o >>= 1) p += __shfl_xor_sync(0xffffffffu, p, o);

        float mn  = fmaxf(m, p);
        float c1  = expf(m - mn);
        float wgt = expf(p - mn);
        d = d * c1 + wgt;
        acc.x = acc.x * c1 + wgt * a.x;
        acc.y = acc.y * c1 + wgt * a.y;
        acc.z = acc.z * c1 + wgt * a.z;
        acc.w = acc.w * c1 + wgt * a.w;
        m = mn;
    }

    float inv = 1.f / (d + 1e-16f);
    float4 b4 = *(const float4*)(bias + lane * 4);
    float o0 = acc.x * inv + b4.x;
    float o1 = acc.y * inv + b4.y;
    float o2 = acc.z * inv + b4.z;
    float o3 = acc.w * inv + b4.w;
    if (slope > 0.f) {
        o0 = (o0 > 0.f) ? o0 : slope * o0;
        o1 = (o1 > 0.f) ? o1 : slope * o1;
        o2 = (o2 > 0.f) ? o2 : slope * o2;
        o3 = (o3 > 0.f) ? o3 : slope * o3;
    }
    *(float4*)(out + (size_t)w * D + lane * 4) = make_float4(o0, o1, o2, o3);
}

// ---------------- GATv2 aggregate, Dout=7 ------------------------------------
__global__ void k_gat7(const float* __restrict__ xl, const float* __restrict__ xr,
                       const float* __restrict__ att, const float* __restrict__ bias,
                       float* __restrict__ out, int M) {
    int w = (blockIdx.x * blockDim.x + threadIdx.x) >> 5;
    int lane = threadIdx.x & 31;
    if (w >= M) return;

    float xrv = (lane < CH) ? xr[w * CH + lane] : 0.f;
    float atv = (lane < CH) ? att[lane] : 0.f;
    int beg = g_off[w], end = g_off[w + 1];

    float m = -INFINITY, d = 0.f, acc = 0.f;
    for (int e = beg; e < end; e++) {
        int s = g_csr[e];
        float av = (lane < CH) ? xl[s * CH + lane] : 0.f;
        float t = av + xrv; t = (t > 0.f) ? t : 0.2f * t;
        float p = t * atv;
        #pragma unroll
        for (int o = 16; o; o >>= 1) p += __shfl_xor_sync(0xffffffffu, p, o);
        float mn  = fmaxf(m, p);
        float c1  = expf(m - mn);
        float wgt = expf(p - mn);
        d = d * c1 + wgt;
        acc = acc * c1 + wgt * av;
        m = mn;
    }
    if (lane < CH)
        out[w * CH + lane] = acc / (d + 1e-16f) + bias[lane];
}

// ---------------- small GEMM: C[M,7] = A[M,128] @ W[128,7] + bias ------------
__global__ void k_gemm7(const float* __restrict__ A, const float* __restrict__ W,
                        const float* __restrict__ bias, float* __restrict__ C, int M) {
    __shared__ float Ws[D * CH];
    for (int i = threadIdx.x; i < D * CH; i += blockDim.x) Ws[i] = W[i];
    __syncthreads();
    int gid = blockIdx.x * blockDim.x + threadIdx.x;
    int row = gid >> 3, c = gid & 7;
    if (row >= M || c >= CH) return;
    const float* a = A + (size_t)row * D;
    float s = 0.f;
    #pragma unroll 8
    for (int k = 0; k < D; k++) s += a[k] * Ws[k * CH + c];
    C[row * CH + c] = s + bias[c];
}

// ---------------- actor head: softmax + gumbel + top-4 + sel -----------------
__global__ void k_actor(const float* __restrict__ logits, const float* __restrict__ gu,
                        float* __restrict__ out, int B, int N) {
    __shared__ float shp[4][NC][CH];
    int tid = threadIdx.x;            // 32 threads
    int b = tid >> 3, i = tid & 7;
    bool active = tid < B * NC;
    if (active) {
        int row = b * N + i;
        float l[CH], mx = -INFINITY;
        for (int c = 0; c < CH; c++) { l[c] = logits[row * CH + c]; mx = fmaxf(mx, l[c]); }
        float s = 0.f;
        for (int c = 0; c < CH; c++) { l[c] = expf(l[c] - mx); s += l[c]; }
        for (int c = 0; c < CH; c++) shp[b][i][c] = l[c] / s;
    }
    __syncthreads();
    if (active) {
        float sc[CH];
        for (int c = 0; c < CH; c++) {
            float u = gu[(b * NC + i) * CH + c];
            float g = -logf(-logf(u));
            sc[c] = logf(shp[b][i][c]) + g;
        }
        int base = (b * NC + i) * NS;
        int seloff = B * NC * NS;
        for (int j = 0; j < NS; j++) {
            int best = 0; float bv = -INFINITY;
            for (int c = 0; c < CH; c++)
                if (sc[c] > bv) { bv = sc[c]; best = c; }
            out[base + j] = (float)best;
            out[seloff + base + j] = shp[b][best][j];
            sc[best] = -INFINITY;
        }
    }
}

// ---------------- value head -------------------------------------------------
__global__ void k_value(const float* __restrict__ H, const float* __restrict__ W,
                        const float* __restrict__ b, float* __restrict__ out, int M) {
    int w = (blockIdx.x * blockDim.x + threadIdx.x) >> 5;
    int lane = threadIdx.x & 31;
    if (w >= M) return;
    float4 h4 = *(const float4*)(H + (size_t)w * D + lane * 4);
    float4 w4 = *(const float4*)(W + lane * 4);
    float p = h4.x * w4.x + h4.y * w4.y + h4.z * w4.z + h4.w * w4.w;
    #pragma unroll
    for (int o = 16; o; o >>= 1) p += __shfl_xor_sync(0xffffffffu, p, o);
    if (lane == 0) out[w] = p + b[0];
}

// ---------------- launch -----------------------------------------------------
extern "C" void kernel_launch(void* const* d_in, const int* in_sizes, int n_in,
                              void* d_out, int out_size) {
    const float* x  = (const float*)d_in[0];
    const int*   ei = (const int*)d_in[1];
    const float* gu = (const float*)d_in[2];
    const float* Wp[4][6];
    for (int l = 0; l < 4; l++)
        for (int j = 0; j < 6; j++)
            Wp[l][j] = (const float*)d_in[3 + l * 6 + j];
    const float* fcW = (const float*)d_in[27];
    const float* fcb = (const float*)d_in[28];

    int M = in_sizes[0] / D;
    int E = in_sizes[1] / 2;
    int B = in_sizes[2] / (NC * CH);
    int N = M / B;
    int ET = E + M;
    float* out = (float*)d_out;

    void *pc, *pxl, *pxr, *ph, *ph2, *ps1, *ps2, *plg;
    cudaGetSymbolAddress(&pc,  g_count);
    cudaGetSymbolAddress(&pxl, g_xl);
    cudaGetSymbolAddress(&pxr, g_xr);
    cudaGetSymbolAddress(&ph,  g_h);
    cudaGetSymbolAddress(&ph2, g_h2);
    cudaGetSymbolAddress(&ps1, g_s1);
    cudaGetSymbolAddress(&ps2, g_s2);
    cudaGetSymbolAddress(&plg, g_lg);
    float* xl = (float*)pxl; float* xr = (float*)pxr;
    float* h  = (float*)ph;  float* h2 = (float*)ph2;
    float* s1 = (float*)ps1; float* s2 = (float*)ps2;
    float* lg = (float*)plg;

    const int tb = 256;
    // ---- CSR build (same graph reused by all 4 GAT layers) ----
    cudaMemsetAsync(pc, 0, (size_t)(M + 1) * sizeof(int));
    int gE = (ET + tb - 1) / tb; if (gE > 4096) gE = 4096;
    k_hist<<<gE, tb>>>(ei + E, E, M);
    k_scan<<<1, 1024>>>(M);
    k_scatter<<<gE, tb>>>(ei, ei + E, E, M);
    k_sortseg<<<(M + tb - 1) / tb, tb>>>(M);

    // ---- GEMM config ----
    size_t smem = 2 * D * D * sizeof(float);  // 128 KB
    cudaFuncSetAttribute(k_sgemm, cudaFuncAttributeMaxDynamicSharedMemorySize, (int)smem);
    int gg = (M + 127) / 128;
    int gw = (M * 32 + tb - 1) / tb;
    int g7 = (M * 8 + tb - 1) / tb;

    // ---- actor path ----
    k_sgemm<<<gg, tb, smem>>>(x, Wp[0][0], Wp[0][1], xl, M);
    k_sgemm<<<gg, tb, smem>>>(x, Wp[0][2], Wp[0][3], xr, M);
    k_gat128<<<gw, tb>>>(xl, xr, Wp[0][4], Wp[0][5], h, M, 0.01f);
    k_gemm7<<<g7, tb>>>(h, Wp[1][0], Wp[1][1], s1, M);
    k_gemm7<<<g7, tb>>>(h, Wp[1][2], Wp[1][3], s2, M);
    k_gat7<<<gw, tb>>>(s1, s2, Wp[1][4], Wp[1][5], lg, M);
    k_actor<<<1, 32>>>(lg, gu, out, B, N);

    // ---- critic path ----
    k_sgemm<<<gg, tb, smem>>>(x, Wp[2][0], Wp[2][1], xl, M);
    k_sgemm<<<gg, tb, smem>>>(x, Wp[2][2], Wp[2][3], xr, M);
    k_gat128<<<gw, tb>>>(xl, xr, Wp[2][4], Wp[2][5], h2, M, 0.01f);
    k_sgemm<<<gg, tb, smem>>>(h2, Wp[3][0], Wp[3][1], xl, M);
    k_sgemm<<<gg, tb, smem>>>(h2, Wp[3][2], Wp[3][3], xr, M);
    k_gat128<<<gw, tb>>>(xl, xr, Wp[3][4], Wp[3][5], h, M, 0.f);
    k_value<<<gw, tb>>>(h, fcW, fcb, out + 2 * B * NC * NS, M);
}